// round 1
// baseline (speedup 1.0000x reference)
#include <cuda_runtime.h>
#include <cuda_bf16.h>
#include <cstdint>

// Problem constants
#define B_   128
#define L_   336
#define N_   321
#define E_   128
#define LAT_ 64

// Output layout (flat, in reference return order): h, h_hat, mu, var
#define H_SZ    (B_ * N_ * E_)      // 5,259,264
#define MU_SZ   (B_ * N_ * LAT_)    // 2,629,632
#define OFF_H   0
#define OFF_HH  (H_SZ)              // 5,259,264
#define OFF_MU  (2 * H_SZ)          // 10,518,528
#define OFF_VAR (2 * H_SZ + MU_SZ)  // 13,148,160

// Scratch: x transposed to [N][B][L] so per-channel GEMM A-reads are contiguous.
__device__ float g_xp[(size_t)N_ * B_ * L_];

// ---------------------------------------------------------------------------
// Packed fp32x2 FMA (sm_100+): double-rate fp32
// ---------------------------------------------------------------------------
union F2U { float2 f; unsigned long long u; };
__device__ __forceinline__ float2 ffma2(float2 a, float2 b, float2 c) {
    F2U A, Bv, C;
    A.f = a; Bv.f = b; C.f = c;
    asm("fma.rn.f32x2 %0, %1, %2, %3;"
        : "=l"(C.u) : "l"(A.u), "l"(Bv.u), "l"(C.u));
    return C.f;
}

// ---------------------------------------------------------------------------
// Kernel 1: transpose x [B, L, N] -> xp [N, B, L]
// ---------------------------------------------------------------------------
__global__ void transpose_kernel(const float* __restrict__ x, float* __restrict__ xp) {
    __shared__ float t[32][33];
    const int b  = blockIdx.z;
    const int n0 = blockIdx.x * 32;
    const int l0 = blockIdx.y * 32;
    const int tx = threadIdx.x, ty = threadIdx.y;

    const float* xb = x + (size_t)b * L_ * N_;
#pragma unroll
    for (int i = 0; i < 32; i += 8) {
        int l = l0 + ty + i, nn = n0 + tx;
        if (l < L_ && nn < N_)
            t[ty + i][tx] = xb[l * N_ + nn];
    }
    __syncthreads();
#pragma unroll
    for (int i = 0; i < 32; i += 8) {
        int nn = n0 + ty + i, l = l0 + tx;
        if (nn < N_ && l < L_)
            xp[(size_t)nn * B_ * L_ + b * L_ + l] = t[tx][ty + i];
    }
}

// ---------------------------------------------------------------------------
// Kernel 2: per-channel GEMM1 + bias + sigmoid gate.
//   h[b,n,e]  = sum_l xp[n,b,l] * W_embed[n,l,e] + b_embed[n,e]
//   hh[b,n,e] = sigmoid(time_x[b,n,e]) * h
// One CTA per channel n: C tile 128x128, K=336 (21 x BK=16), double-buffered.
// ---------------------------------------------------------------------------
#define BK 16

__global__ __launch_bounds__(256, 2)
void gemm1_kernel(const float* __restrict__ xp,
                  const float* __restrict__ We,    // [N][L][E]
                  const float* __restrict__ be,    // [N][E]
                  const float* __restrict__ txg,   // [B][N][E]
                  float* __restrict__ out)
{
    const int n = blockIdx.x;
    const float* A  = xp + (size_t)n * B_ * L_;   // row stride L_
    const float* Bw = We + (size_t)n * L_ * E_;   // row stride E_

    __shared__ float As[2][BK][128];
    __shared__ float Bs[2][BK][128];

    const int tid = threadIdx.x;
    const int tx = tid & 15, ty = tid >> 4;

    float4 ra[2], rb[2];
    float2 c[8][4];
#pragma unroll
    for (int i = 0; i < 8; i++)
#pragma unroll
        for (int j = 0; j < 4; j++) c[i][j] = make_float2(0.f, 0.f);

    auto ldg = [&](int kt) {
        const int k0 = kt * BK;
#pragma unroll
        for (int i = 0; i < 2; i++) {
            int idx = tid + i * 256;
            int m = idx >> 2, c4 = (idx & 3) * 4;
            ra[i] = *(const float4*)(A + m * L_ + k0 + c4);
            int r = idx >> 5, e4 = (idx & 31) * 4;
            rb[i] = *(const float4*)(Bw + (k0 + r) * E_ + e4);
        }
    };
    auto sts = [&](int buf) {
#pragma unroll
        for (int i = 0; i < 2; i++) {
            int idx = tid + i * 256;
            int m = idx >> 2, c4 = (idx & 3) * 4;
            As[buf][c4 + 0][m] = ra[i].x;
            As[buf][c4 + 1][m] = ra[i].y;
            As[buf][c4 + 2][m] = ra[i].z;
            As[buf][c4 + 3][m] = ra[i].w;
            int r = idx >> 5, e4 = (idx & 31) * 4;
            *(float4*)&Bs[buf][r][e4] = rb[i];
        }
    };

    ldg(0); sts(0);
    __syncthreads();

    const int NT = L_ / BK;  // 21
    for (int kt = 0; kt < NT; kt++) {
        const int cur = kt & 1;
        if (kt + 1 < NT) ldg(kt + 1);
#pragma unroll
        for (int k = 0; k < BK; k++) {
            float a[8]; float2 b2[4];
            *(float4*)&a[0]  = *(const float4*)&As[cur][k][ty * 8];
            *(float4*)&a[4]  = *(const float4*)&As[cur][k][ty * 8 + 4];
            *(float4*)&b2[0] = *(const float4*)&Bs[cur][k][tx * 8];
            *(float4*)&b2[2] = *(const float4*)&Bs[cur][k][tx * 8 + 4];
#pragma unroll
            for (int i = 0; i < 8; i++) {
                float2 ap = make_float2(a[i], a[i]);
#pragma unroll
                for (int j = 0; j < 4; j++)
                    c[i][j] = ffma2(ap, b2[j], c[i][j]);
            }
        }
        if (kt + 1 < NT) { sts(cur ^ 1); }
        __syncthreads();
    }

    // Epilogue: bias, write h; sigmoid gate with time_x, write h_hat.
    const int mbase = ty * 8;
    const int ebase = tx * 8;
    float bv[8];
    *(float4*)&bv[0] = *(const float4*)(be + n * E_ + ebase);
    *(float4*)&bv[4] = *(const float4*)(be + n * E_ + ebase + 4);

    float* out_h  = out + OFF_H;
    float* out_hh = out + OFF_HH;
#pragma unroll
    for (int i = 0; i < 8; i++) {
        const int b = mbase + i;
        const int o = b * (N_ * E_) + n * E_ + ebase;
        float h[8];
        h[0] = c[i][0].x + bv[0]; h[1] = c[i][0].y + bv[1];
        h[2] = c[i][1].x + bv[2]; h[3] = c[i][1].y + bv[3];
        h[4] = c[i][2].x + bv[4]; h[5] = c[i][2].y + bv[5];
        h[6] = c[i][3].x + bv[6]; h[7] = c[i][3].y + bv[7];
        *(float4*)(out_h + o)     = *(float4*)&h[0];
        *(float4*)(out_h + o + 4) = *(float4*)&h[4];

        float t[8];
        *(float4*)&t[0] = *(const float4*)(txg + o);
        *(float4*)&t[4] = *(const float4*)(txg + o + 4);
        float hh[8];
#pragma unroll
        for (int j = 0; j < 8; j++) {
            float s = 1.0f / (1.0f + __expf(-t[j]));
            hh[j] = s * h[j];
        }
        *(float4*)(out_hh + o)     = *(float4*)&hh[0];
        *(float4*)(out_hh + o + 4) = *(float4*)&hh[4];
    }
}

// ---------------------------------------------------------------------------
// Kernel 3: per-channel GEMM2/3 fused:
//   mu[b,n,k]  = sum_e hh[b,n,e] * W_mu[n,e,k]  + b_mu[n,k]
//   var[b,n,k] = sum_e hh[b,n,e] * W_var[n,e,k] + b_var[n,k]
// Weight concatenated along output dim: cols [0,64) = mu, [64,128) = var.
// A = h_hat read from d_out (row stride N_*E_). K = E_ = 128 (8 k-tiles).
// ---------------------------------------------------------------------------
__global__ __launch_bounds__(256, 2)
void gemm2_kernel(const float* __restrict__ outc,  // = d_out (reads h_hat region)
                  const float* __restrict__ Wmu,   // [N][E][LAT]
                  const float* __restrict__ bmu,   // [N][LAT]
                  const float* __restrict__ Wvar,  // [N][E][LAT]
                  const float* __restrict__ bvar,  // [N][LAT]
                  float* __restrict__ out)
{
    const int n = blockIdx.x;
    const float* A = outc + OFF_HH + n * E_;      // row stride N_*E_
    const float* Wm = Wmu  + (size_t)n * E_ * LAT_;
    const float* Wv = Wvar + (size_t)n * E_ * LAT_;

    __shared__ float As[2][BK][128];
    __shared__ float Bs[2][BK][128];

    const int tid = threadIdx.x;
    const int tx = tid & 15, ty = tid >> 4;

    float4 ra[2], rb[2];
    float2 c[8][4];
#pragma unroll
    for (int i = 0; i < 8; i++)
#pragma unroll
        for (int j = 0; j < 4; j++) c[i][j] = make_float2(0.f, 0.f);

    auto ldg = [&](int kt) {
        const int k0 = kt * BK;
#pragma unroll
        for (int i = 0; i < 2; i++) {
            int idx = tid + i * 256;
            int m = idx >> 2, c4 = (idx & 3) * 4;
            ra[i] = *(const float4*)(A + m * (N_ * E_) + k0 + c4);
            int r = idx >> 5, j4 = (idx & 31) * 4;   // j4: output col
            const int e = k0 + r;
            const float* src = (j4 < 64) ? (Wm + e * LAT_ + j4)
                                         : (Wv + e * LAT_ + (j4 - 64));
            rb[i] = *(const float4*)src;
        }
    };
    auto sts = [&](int buf) {
#pragma unroll
        for (int i = 0; i < 2; i++) {
            int idx = tid + i * 256;
            int m = idx >> 2, c4 = (idx & 3) * 4;
            As[buf][c4 + 0][m] = ra[i].x;
            As[buf][c4 + 1][m] = ra[i].y;
            As[buf][c4 + 2][m] = ra[i].z;
            As[buf][c4 + 3][m] = ra[i].w;
            int r = idx >> 5, j4 = (idx & 31) * 4;
            *(float4*)&Bs[buf][r][j4] = rb[i];
        }
    };

    ldg(0); sts(0);
    __syncthreads();

    const int NT = E_ / BK;  // 8
    for (int kt = 0; kt < NT; kt++) {
        const int cur = kt & 1;
        if (kt + 1 < NT) ldg(kt + 1);
#pragma unroll
        for (int k = 0; k < BK; k++) {
            float a[8]; float2 b2[4];
            *(float4*)&a[0]  = *(const float4*)&As[cur][k][ty * 8];
            *(float4*)&a[4]  = *(const float4*)&As[cur][k][ty * 8 + 4];
            *(float4*)&b2[0] = *(const float4*)&Bs[cur][k][tx * 8];
            *(float4*)&b2[2] = *(const float4*)&Bs[cur][k][tx * 8 + 4];
#pragma unroll
            for (int i = 0; i < 8; i++) {
                float2 ap = make_float2(a[i], a[i]);
#pragma unroll
                for (int j = 0; j < 4; j++)
                    c[i][j] = ffma2(ap, b2[j], c[i][j]);
            }
        }
        if (kt + 1 < NT) { sts(cur ^ 1); }
        __syncthreads();
    }

    // Epilogue: cols [0,64) -> mu, [64,128) -> var. Each thread owns 8
    // consecutive cols entirely inside one of the two halves.
    const int mbase = ty * 8;
    const int jfull = tx * 8;
    const bool is_mu = (jfull < 64);
    const int jb = is_mu ? jfull : (jfull - 64);
    const float* bp = (is_mu ? bmu : bvar) + n * LAT_ + jb;
    const int OFFO = is_mu ? OFF_MU : OFF_VAR;

    float bv[8];
    *(float4*)&bv[0] = *(const float4*)(bp);
    *(float4*)&bv[4] = *(const float4*)(bp + 4);

#pragma unroll
    for (int i = 0; i < 8; i++) {
        const int b = mbase + i;
        const int o = OFFO + b * (N_ * LAT_) + n * LAT_ + jb;
        float v[8];
        v[0] = c[i][0].x + bv[0]; v[1] = c[i][0].y + bv[1];
        v[2] = c[i][1].x + bv[2]; v[3] = c[i][1].y + bv[3];
        v[4] = c[i][2].x + bv[4]; v[5] = c[i][2].y + bv[5];
        v[6] = c[i][3].x + bv[6]; v[7] = c[i][3].y + bv[7];
        *(float4*)(out + o)     = *(float4*)&v[0];
        *(float4*)(out + o + 4) = *(float4*)&v[4];
    }
}

// ---------------------------------------------------------------------------
extern "C" void kernel_launch(void* const* d_in, const int* in_sizes, int n_in,
                              void* d_out, int out_size) {
    const float* x    = (const float*)d_in[0];
    const float* txg  = (const float*)d_in[1];
    const float* We   = (const float*)d_in[2];
    const float* be   = (const float*)d_in[3];
    const float* Wmu  = (const float*)d_in[4];
    const float* bmu  = (const float*)d_in[5];
    const float* Wvar = (const float*)d_in[6];
    const float* bvar = (const float*)d_in[7];
    float* out = (float*)d_out;

    float* xp;
    cudaGetSymbolAddress((void**)&xp, g_xp);

    dim3 tgrid((N_ + 31) / 32, (L_ + 31) / 32, B_);
    transpose_kernel<<<tgrid, dim3(32, 8)>>>(x, xp);
    gemm1_kernel<<<N_, 256>>>(xp, We, be, txg, out);
    gemm2_kernel<<<N_, 256>>>(out, Wmu, bmu, Wvar, bvar, out);
}